// round 6
// baseline (speedup 1.0000x reference)
#include <cuda_runtime.h>
#include <cstdint>

// ============================================================================
// EdgeMLP: concat -> GEMM1(tf32 mma.sync) -> LayerNorm -> SiLU ->
//          GEMM2(tf32 mma.sync) -> SiLU -> out
// Baseline-PTX only (toolchain emits .target sm_103; no tcgen05/cluster).
// 1 CTA = 128 rows. 512 threads = 16 warps in 4(M) x 4(N) layout.
// Operands in SMEM packed per-lane-wide: A frag = uint4 (LDS.128),
// B frag = uint2 (LDS.64); staged by gather so all wide STS are
// lane-contiguous and conflict-free.
// ============================================================================

#define TILE_M 128
#define NKS1   24     // 192/8 k-steps for GEMM1
#define NKS2   16     // 128/8 k-steps for GEMM2
#define NTHR   512

// dynamic SMEM layout (float offsets)
#define R0_OFF   0        // 24576 floats: A1 frags (8*24*32 uint4) -> A2 frags
#define R1_OFF   24576    // 24576 floats: B1 frags (16*24*32 uint2) -> W2 frags
#define MISC_OFF 49152    // b1,g,be,b2 (4*128) + red (2*4*128)
#define SMEM_FLOATS (49152 + 512 + 1024)
#define SMEM_BYTES  (SMEM_FLOATS * 4)

static __device__ __forceinline__ uint32_t f2tf32(float f) {
    uint32_t r;
    asm("cvt.rna.tf32.f32 %0, %1;" : "=r"(r) : "f"(f));
    return r;
}
static __device__ __forceinline__ float silu_f(float x) {
    return __fdividef(x, 1.f + __expf(-x));
}
static __device__ __forceinline__ void mma8(float* c, const uint32_t* a,
                                            uint32_t b0, uint32_t b1) {
    asm volatile(
        "mma.sync.aligned.m16n8k8.row.col.f32.tf32.tf32.f32 "
        "{%0,%1,%2,%3},{%4,%5,%6,%7},{%8,%9},{%0,%1,%2,%3};\n"
        : "+f"(c[0]), "+f"(c[1]), "+f"(c[2]), "+f"(c[3])
        : "r"(a[0]), "r"(a[1]), "r"(a[2]), "r"(a[3]), "r"(b0), "r"(b1));
}

// Packed layouts:
//  A region: uint4 AQ[(mt*NKS + ks)*32 + lane]
//    lane = g*4+tig holds words {(r=g,c=tig),(g+8,tig),(g,tig+4),(g+8,tig+4)}
//    of the 16x8 tf32 block (mt = row/16, ks = col/8)  [mma A-frag order]
//  B region: uint2 BQ[(nbg*NKS + ks)*32 + lane]
//    lane holds {(k=tig,n=g),(k=tig+4,n=g)} of block (nbg = n/8, ks = k/8)

__global__ void __launch_bounds__(NTHR, 1)
edge_mlp_kernel(const float* __restrict__ src, const float* __restrict__ edge,
                const float* __restrict__ W1, const float* __restrict__ b1,
                const float* __restrict__ gamma, const float* __restrict__ beta,
                const float* __restrict__ W2, const float* __restrict__ b2,
                float* __restrict__ out, int E) {
    extern __shared__ float sm[];
    float* s_b1 = sm + MISC_OFF;
    float* s_g  = s_b1 + 128;
    float* s_be = s_g + 128;
    float* s_b2 = s_be + 128;
    float* red  = s_b2 + 128;     // [stat(2)][nw(4)][row(128)]

    uint4* AQ = (uint4*)(sm + R0_OFF);   // A1 frags, later A2 frags
    uint2* BQ = (uint2*)(sm + R1_OFF);   // B1 frags, later W2 frags

    const int tid  = threadIdx.x;
    const int lane = tid & 31;
    const int wid  = tid >> 5;
    const int mw   = wid >> 2;    // 0..3 : rows 32*mw .. 32*mw+31
    const int nw   = wid & 3;     // 0..3 : cols 32*nw .. 32*nw+31
    const int g    = lane >> 2;
    const int tig  = lane & 3;
    const int mt0  = mw * 2;
    const int nb0  = nw * 4;

    const long long r0 = (long long)blockIdx.x * TILE_M;

    // ---------------- stage A1 (concat src|edge): gather one uint4/thread ---
    // 8 mt * 24 ks * 32 lanes = 6144 groups
    #pragma unroll
    for (int u = tid; u < 8 * NKS1 * 32; u += NTHR) {
        int ls = u & 31;
        int f  = u >> 5;
        int ks = f % NKS1;
        int mt = f / NKS1;
        int gg = ls >> 2, tg = ls & 3;
        int rowa = mt * 16 + gg;            // and rowa+8
        long long gra = r0 + rowa;
        long long grb = gra + 8;
        float v00 = 0.f, v01 = 0.f, v10 = 0.f, v11 = 0.f;
        if (ks < 16) {
            int c0 = ks * 8 + tg;
            if (gra < E) { v00 = __ldg(src + gra * 128 + c0);
                           v01 = __ldg(src + gra * 128 + c0 + 4); }
            if (grb < E) { v10 = __ldg(src + grb * 128 + c0);
                           v11 = __ldg(src + grb * 128 + c0 + 4); }
        } else {
            int c0 = (ks - 16) * 8 + tg;
            if (gra < E) { v00 = __ldg(edge + gra * 64 + c0);
                           v01 = __ldg(edge + gra * 64 + c0 + 4); }
            if (grb < E) { v10 = __ldg(edge + grb * 64 + c0);
                           v11 = __ldg(edge + grb * 64 + c0 + 4); }
        }
        uint4 t;
        t.x = f2tf32(v00); t.y = f2tf32(v10); t.z = f2tf32(v01); t.w = f2tf32(v11);
        AQ[f * 32 + ls] = t;
    }
    // ---------------- stage B1 = W1 frags: gather one uint2/thread ----------
    // 16 nbg * 24 ks * 32 lanes = 12288 groups
    #pragma unroll
    for (int u = tid; u < 16 * NKS1 * 32; u += NTHR) {
        int ls = u & 31;
        int f  = u >> 5;
        int ks = f % NKS1;
        int nbg = f / NKS1;
        int gg = ls >> 2, tg = ls & 3;
        int k0 = ks * 8 + tg;
        int n  = nbg * 8 + gg;
        uint2 t;
        t.x = f2tf32(__ldg(W1 + k0 * 128 + n));
        t.y = f2tf32(__ldg(W1 + (k0 + 4) * 128 + n));
        BQ[f * 32 + ls] = t;
    }
    if (tid < 128) {
        s_b1[tid] = b1[tid];
        s_g[tid]  = gamma[tid];
        s_be[tid] = beta[tid];
        s_b2[tid] = b2[tid];
    }
    __syncthreads();

    // ---------------- GEMM1: h = x @ W1 -------------------------------------
    float acc[2][4][4];
    #pragma unroll
    for (int m2 = 0; m2 < 2; m2++)
        #pragma unroll
        for (int nb = 0; nb < 4; nb++)
            #pragma unroll
            for (int j = 0; j < 4; j++) acc[m2][nb][j] = 0.f;

    {
        const uint4* A0 = AQ + (mt0 * NKS1) * 32 + lane;
        const uint4* A1 = AQ + ((mt0 + 1) * NKS1) * 32 + lane;
        const uint2* B0 = BQ + (nb0 * NKS1) * 32 + lane;
        #pragma unroll
        for (int ks = 0; ks < NKS1; ks++) {
            uint4 a0 = A0[ks * 32];
            uint4 a1 = A1[ks * 32];
            #pragma unroll
            for (int nb = 0; nb < 4; nb++) {
                uint2 b = B0[(nb * NKS1 + ks) * 32];
                mma8(acc[0][nb], (const uint32_t*)&a0, b.x, b.y);
                mma8(acc[1][nb], (const uint32_t*)&a1, b.x, b.y);
            }
        }
    }

    // ---------------- bias + row stats (sum, sumsq) -------------------------
    float s_[2][2] = {{0.f, 0.f}, {0.f, 0.f}};
    float q_[2][2] = {{0.f, 0.f}, {0.f, 0.f}};
    #pragma unroll
    for (int m2 = 0; m2 < 2; m2++)
        #pragma unroll
        for (int nb = 0; nb < 4; nb++) {
            int n0 = (nb0 + nb) * 8 + tig * 2;
            float bb0 = s_b1[n0], bb1 = s_b1[n0 + 1];
            #pragma unroll
            for (int h = 0; h < 2; h++) {
                float v0 = acc[m2][nb][h * 2]     + bb0;
                float v1 = acc[m2][nb][h * 2 + 1] + bb1;
                acc[m2][nb][h * 2]     = v0;
                acc[m2][nb][h * 2 + 1] = v1;
                s_[m2][h] += v0 + v1;
                q_[m2][h] += v0 * v0 + v1 * v1;
            }
        }
    #pragma unroll
    for (int m2 = 0; m2 < 2; m2++)
        #pragma unroll
        for (int h = 0; h < 2; h++) {
            s_[m2][h] += __shfl_xor_sync(0xffffffffu, s_[m2][h], 1);
            s_[m2][h] += __shfl_xor_sync(0xffffffffu, s_[m2][h], 2);
            q_[m2][h] += __shfl_xor_sync(0xffffffffu, q_[m2][h], 1);
            q_[m2][h] += __shfl_xor_sync(0xffffffffu, q_[m2][h], 2);
        }
    if (tig == 0) {
        #pragma unroll
        for (int m2 = 0; m2 < 2; m2++)
            #pragma unroll
            for (int h = 0; h < 2; h++) {
                int row = mw * 32 + m2 * 16 + h * 8 + g;
                red[(0 * 4 + nw) * 128 + row] = s_[m2][h];
                red[(1 * 4 + nw) * 128 + row] = q_[m2][h];
            }
    }
    __syncthreads();   // GEMM1 fully retired CTA-wide; RA/RB reusable

    // ---------------- stage W2 frags (into BQ region) -----------------------
    // 16 nbg * 16 ks * 32 lanes = 8192 groups
    #pragma unroll
    for (int u = tid; u < 16 * NKS2 * 32; u += NTHR) {
        int ls = u & 31;
        int f  = u >> 5;
        int ks = f & (NKS2 - 1);
        int nbg = f >> 4;
        int gg = ls >> 2, tg = ls & 3;
        int k0 = ks * 8 + tg;
        int n  = nbg * 8 + gg;
        uint2 t;
        t.x = f2tf32(__ldg(W2 + k0 * 128 + n));
        t.y = f2tf32(__ldg(W2 + (k0 + 4) * 128 + n));
        BQ[f * 32 + ls] = t;
    }

    // ---------------- LayerNorm + SiLU -> A2 frags (into AQ region) ---------
    {
        uint32_t* AF = (uint32_t*)AQ;
        #pragma unroll
        for (int m2 = 0; m2 < 2; m2++)
            #pragma unroll
            for (int h = 0; h < 2; h++) {
                int row = mw * 32 + m2 * 16 + h * 8 + g;
                float mu = (red[0 * 128 + row] + red[1 * 128 + row] +
                            red[2 * 128 + row] + red[3 * 128 + row]) * (1.f / 128.f);
                float ms = (red[4 * 128 + row] + red[5 * 128 + row] +
                            red[6 * 128 + row] + red[7 * 128 + row]) * (1.f / 128.f);
                float var = ms - mu * mu;
                float rstd = rsqrtf(fmaxf(var, 0.f) + 1e-5f);
                int w = h + 2 * (tig >> 1);
                #pragma unroll
                for (int nb = 0; nb < 4; nb++) {
                    int nbg = nb0 + nb;
                    int n0 = nbg * 8 + tig * 2;
                    float x0 = (acc[m2][nb][h * 2]     - mu) * rstd * s_g[n0]     + s_be[n0];
                    float x1 = (acc[m2][nb][h * 2 + 1] - mu) * rstd * s_g[n0 + 1] + s_be[n0 + 1];
                    int idx = (((mt0 + m2) * NKS2 + nbg) * 32 + g * 4 + 2 * (tig & 1));
                    AF[idx * 4 + w]     = f2tf32(silu_f(x0));
                    AF[idx * 4 + 4 + w] = f2tf32(silu_f(x1));
                }
            }
    }
    __syncthreads();

    // ---------------- GEMM2: y = a2 @ W2 ------------------------------------
    float acc2[2][4][4];
    #pragma unroll
    for (int m2 = 0; m2 < 2; m2++)
        #pragma unroll
        for (int nb = 0; nb < 4; nb++)
            #pragma unroll
            for (int j = 0; j < 4; j++) acc2[m2][nb][j] = 0.f;

    {
        const uint4* A0 = AQ + (mt0 * NKS2) * 32 + lane;
        const uint4* A1 = AQ + ((mt0 + 1) * NKS2) * 32 + lane;
        const uint2* B0 = BQ + (nb0 * NKS2) * 32 + lane;
        #pragma unroll
        for (int ks = 0; ks < NKS2; ks++) {
            uint4 a0 = A0[ks * 32];
            uint4 a1 = A1[ks * 32];
            #pragma unroll
            for (int nb = 0; nb < 4; nb++) {
                uint2 b = B0[(nb * NKS2 + ks) * 32];
                mma8(acc2[0][nb], (const uint32_t*)&a0, b.x, b.y);
                mma8(acc2[1][nb], (const uint32_t*)&a1, b.x, b.y);
            }
        }
    }

    // ---------------- epilogue: +b2, SiLU, store ----------------------------
    #pragma unroll
    for (int m2 = 0; m2 < 2; m2++)
        #pragma unroll
        for (int h = 0; h < 2; h++) {
            long long row = r0 + mw * 32 + m2 * 16 + h * 8 + g;
            if (row < E) {
                #pragma unroll
                for (int nb = 0; nb < 4; nb++) {
                    int n0 = (nb0 + nb) * 8 + tig * 2;
                    float x0 = acc2[m2][nb][h * 2]     + s_b2[n0];
                    float x1 = acc2[m2][nb][h * 2 + 1] + s_b2[n0 + 1];
                    float2 o;
                    o.x = silu_f(x0);
                    o.y = silu_f(x1);
                    *(float2*)(out + row * 128 + n0) = o;
                }
            }
        }
}

extern "C" void kernel_launch(void* const* d_in, const int* in_sizes, int n_in,
                              void* d_out, int out_size) {
    const float* src   = (const float*)d_in[0];
    const float* edge  = (const float*)d_in[1];
    const float* W1    = (const float*)d_in[2];
    const float* b1    = (const float*)d_in[3];
    const float* gamma = (const float*)d_in[4];
    const float* beta  = (const float*)d_in[5];
    const float* W2    = (const float*)d_in[6];
    const float* b2    = (const float*)d_in[7];
    float* out = (float*)d_out;

    int E = in_sizes[0] / 128;
    int grid = (E + TILE_M - 1) / TILE_M;

    static bool attr_set = false;
    if (!attr_set) {
        cudaFuncSetAttribute(edge_mlp_kernel,
                             cudaFuncAttributeMaxDynamicSharedMemorySize,
                             SMEM_BYTES);
        attr_set = true;
    }
    edge_mlp_kernel<<<grid, NTHR, SMEM_BYTES>>>(src, edge, W1, b1, gamma, beta,
                                                W2, b2, out, E);
}